// round 17
// baseline (speedup 1.0000x reference)
#include <cuda_runtime.h>
#include <cuda_bf16.h>

#define RES 7
#define NROI 1024
#define NCH 256

// ---------------- per-roi precomputed tables ----------------
__device__ int2   g_lb[NROI];          // lvl, batch
__device__ int4   g_yrow[NROI][8];     // 4 row offsets (premultiplied by W) per py
__device__ float4 g_ywt[NROI][8];      // y weights (*0.5, validity folded)
__device__ int4   g_xcol[NROI][8];     // 4 col offsets per px
__device__ float4 g_xwt[NROI][8];      // x weights (*0.5, validity folded)

__device__ __forceinline__ void samp(float v, int size,
                                     int& lo, int& hi, float& wl, float& wh) {
    bool valid = (v >= -1.0f) && (v <= (float)size);
    float v0 = fmaxf(v, 0.0f);
    int l = (int)floorf(v0);
    float fr;
    if (l >= size - 1) { l = size - 1; hi = size - 1; fr = 0.0f; }
    else               { hi = l + 1; fr = v0 - (float)l; }
    lo = l;
    wl = valid ? (1.0f - fr) : 0.0f;
    wh = valid ? fr : 0.0f;
}

__global__ void setup_kernel(const float* __restrict__ p0,
                             const float* __restrict__ p1) {
    int r = blockIdx.x * blockDim.x + threadIdx.x;
    if (r >= NROI) return;
    const float* p = (r < 512) ? (p0 + r * 4) : (p1 + (r - 512) * 4);
    float x1 = p[0], y1 = p[1], x2 = p[2], y2 = p[3];
    float area = (x2 - x1 + 1.0f) * (y2 - y1 + 1.0f);
    float sz = sqrtf(area);
    float lv = floorf(4.0f + log2f(sz / 224.0f + 1e-6f));
    lv = fminf(fmaxf(lv, 2.0f), 5.0f);
    int lvl = (int)lv - 2;
    float scale = 0.25f / (float)(1 << lvl);
    int H, W;
    switch (lvl) {
        case 0:  H = 200; W = 200; break;
        case 1:  H = 100; W = 100; break;
        case 2:  H = 50;  W = 50;  break;
        default: H = 25;  W = 25;  break;
    }
    float x1s = x1 * scale, y1s = y1 * scale;
    float rw = fmaxf(x2 * scale - x1s, 1.0f);
    float rh = fmaxf(y2 * scale - y1s, 1.0f);
    float bw = rw / 7.0f, bh = rh / 7.0f;

    g_lb[r] = make_int2(lvl, (r < 512) ? 0 : 1);

#pragma unroll
    for (int q = 0; q < 7; q++) {
        {   // y samples 2q, 2q+1
            float s0 = y1s + ((float)(2 * q) + 0.5f) * 0.5f * bh;
            float s1 = y1s + ((float)(2 * q + 1) + 0.5f) * 0.5f * bh;
            int l0, h0, l1, h1; float a0, b0, a1, b1;
            samp(s0, H, l0, h0, a0, b0);
            samp(s1, H, l1, h1, a1, b1);
            g_yrow[r][q] = make_int4(l0 * W, h0 * W, l1 * W, h1 * W);
            g_ywt[r][q]  = make_float4(a0 * 0.5f, b0 * 0.5f, a1 * 0.5f, b1 * 0.5f);
        }
        {   // x samples 2q, 2q+1
            float s0 = x1s + ((float)(2 * q) + 0.5f) * 0.5f * bw;
            float s1 = x1s + ((float)(2 * q + 1) + 0.5f) * 0.5f * bw;
            int l0, h0, l1, h1; float a0, b0, a1, b1;
            samp(s0, W, l0, h0, a0, b0);
            samp(s1, W, l1, h1, a1, b1);
            g_xcol[r][q] = make_int4(l0, h0, l1, h1);
            g_xwt[r][q]  = make_float4(a0 * 0.5f, b0 * 0.5f, a1 * 0.5f, b1 * 0.5f);
        }
    }
}

// grid = (NROI, 2), block = 224 (7 warps).
// warp = (roi, py); lane = x-tap (28 taps = 7 px * 4 taps; lanes 28-31 idle).
// Each LDG instruction reads ONE feature row across all lanes (1-2 cache lines).
// Per channel: 4 row-LDGs + 4 FMA + 2 shfl-reduce + store (7 lanes).
__global__ __launch_bounds__(224) void pool_kernel(
    const float* __restrict__ f0, const float* __restrict__ f1,
    const float* __restrict__ f2, const float* __restrict__ f3,
    float* __restrict__ out) {

    const int roi  = blockIdx.x;
    const int half = blockIdx.y;            // channel half: 0 or 1
    const int py   = threadIdx.x >> 5;      // warp id = output row
    const int t    = threadIdx.x & 31;
    const int px   = min(t >> 2, 6);
    const int xi   = t & 3;

    const int2 lb = g_lb[roi];
    const float* base; int HW;
    switch (lb.x) {
        case 0:  base = f0; HW = 200 * 200; break;
        case 1:  base = f1; HW = 100 * 100; break;
        case 2:  base = f2; HW = 50 * 50;   break;
        default: base = f3; HW = 25 * 25;   break;
    }

    // loop-invariant per-lane tap state
    const int   xoff = ((const int*)  &g_xcol[roi][px])[xi];
    const float wx   = ((const float*)&g_xwt[roi][px])[xi];
    const int4   yr  = g_yrow[roi][py];
    const float4 wy  = g_ywt[roi][py];

    const float* cb = base + ((size_t)lb.y * NCH + half * 128) * HW;
    const bool wr = (xi == 0) && (t < 28);
    float* op = out + ((size_t)roi * NCH + half * 128) * 49 + py * 7 + (t >> 2);

#pragma unroll 4
    for (int c = 0; c < 128; c++) {
        const float* p = cb + (size_t)c * HW + xoff;
        float v = wy.x * __ldg(p + yr.x) + wy.y * __ldg(p + yr.y)
                + wy.z * __ldg(p + yr.z) + wy.w * __ldg(p + yr.w);
        v *= wx;
        v += __shfl_xor_sync(0xFFFFFFFFu, v, 1);
        v += __shfl_xor_sync(0xFFFFFFFFu, v, 2);
        if (wr) op[(size_t)c * 49] = v;
    }
}

extern "C" void kernel_launch(void* const* d_in, const int* in_sizes, int n_in,
                              void* d_out, int out_size) {
    const float* f0 = (const float*)d_in[0];
    const float* f1 = (const float*)d_in[1];
    const float* f2 = (const float*)d_in[2];
    const float* f3 = (const float*)d_in[3];
    // d_in[4] = feat4 (13x13) — never selected by the 4 RATIOS; unused.
    const float* p0 = (const float*)d_in[5];
    const float* p1 = (const float*)d_in[6];
    float* out = (float*)d_out;

    setup_kernel<<<4, 256>>>(p0, p1);
    dim3 grid(NROI, 2);
    pool_kernel<<<grid, 224>>>(f0, f1, f2, f3, out);
}